// round 10
// baseline (speedup 1.0000x reference)
#include <cuda_runtime.h>
#include <cstdint>

// x: (S=128, B=512, D=512) f32 ; src_mask: (B,S) int32 (nonzero = padded)
// out: (B, G=127, 2*D) f32
// left[b][g][d]  = prefix_{s<=g} x[s][b][d]*valid[b][s]
// right[b][g][d] = total[b][d] - left[b][g][d]
//
// R9 (= R8 with compile fix): masked cumsum per column, prefix tile staged in
// SMEM so the output phase is pure float4 streaming stores (STG.128).
// Hypothesis: LSU store-issue cost of scalar STG.32 throttled the DRAM stream
// in R5-R7 (pinned at ~62-65% DRAM regardless of occupancy).

namespace {
constexpr int S   = 128;
constexpr int B   = 512;
constexpr int D   = 512;
constexpr int G   = S - 1;        // 127
constexpr int CH  = 2;            // s-chunks per column
constexpr int SC  = S / CH;       // 64
constexpr int DPB = 256;          // d-columns per block
constexpr int TPB = DPB * CH;     // 512 threads
constexpr int NBLOCKS_PER_B = D / DPB;   // 2

// dynamic smem layout (floats):
//   pref_s [S][DPB] : 32768
//   tot_s  [DPB]    : 256
//   part0  [DPB]    : 256
//   valid  [S]      : 128
constexpr int OFF_PREF  = 0;
constexpr int OFF_TOT   = S * DPB;
constexpr int OFF_PART0 = OFF_TOT + DPB;
constexpr int OFF_VALID = OFF_PART0 + DPB;
constexpr int SMEM_FLOATS = OFF_VALID + S;
constexpr size_t SMEM_BYTES = SMEM_FLOATS * sizeof(float);
}

__global__ __launch_bounds__(TPB, 1)
void frag_prefix_kernel(const float* __restrict__ x,
                        const int*   __restrict__ mask,
                        float*       __restrict__ out)
{
    extern __shared__ float sm[];
    float* __restrict__ pref_s = sm + OFF_PREF;   // [S][DPB] row-major
    float* __restrict__ tot_s  = sm + OFF_TOT;    // [DPB]
    float* __restrict__ part0  = sm + OFF_PART0;  // [DPB]
    float* __restrict__ valid  = sm + OFF_VALID;  // [S]

    const int tid  = threadIdx.x;
    const int b    = blockIdx.x >> 1;             // / NBLOCKS_PER_B
    const int dblk = blockIdx.x & 1;
    const int dl   = tid & (DPB - 1);             // column within strip
    const int c    = tid >> 8;                    // s-chunk 0/1 (uniform per warp)
    const int d    = dblk * DPB + dl;

    if (tid < S)
        valid[tid] = (mask[b * S + tid] != 0) ? 0.0f : 1.0f;
    __syncthreads();

    // ---- Phase 1: masked prefix of this thread's 64-long s-chunk (regs) ----
    const float* __restrict__ xp =
        x + (size_t)(c * SC) * (B * D) + (size_t)b * D + d;
    float pref[SC];
    float p = 0.0f;
    #pragma unroll
    for (int i = 0; i < SC; ++i) {
        p += __ldcs(xp + (size_t)i * (B * D)) * valid[c * SC + i];
        pref[i] = p;
    }

    if (c == 0) part0[dl] = p;
    __syncthreads();

    const float carry = (c == 1) ? part0[dl] : 0.0f;
    if (c == 1) tot_s[dl] = carry + p;

    // Deposit carry-adjusted prefix into the smem tile (conflict-free:
    // warp = 32 consecutive dl within one row).
    #pragma unroll
    for (int i = 0; i < SC; ++i)
        pref_s[(c * SC + i) * DPB + dl] = pref[i] + carry;
    __syncthreads();

    // ---- Phase 2: vectorized streaming stores (STG.128) ----
    // Per iteration the block covers 4 g-rows: 128 threads per g
    // (64 float4 left + 64 float4 right).
    const int gof  = tid >> 7;          // 0..3: g offset within group of 4
    const int r    = tid & 127;
    const int side = r >> 6;            // 0 = left, 1 = right
    const int cf   = (r & 63) << 2;     // float4 column offset in strip

    const float4 tot4 = *reinterpret_cast<const float4*>(&tot_s[cf]);
    float* __restrict__ ob =
        out + (size_t)b * G * (2 * D) + side * D + dblk * DPB + cf;

    #pragma unroll 4
    for (int gb = 0; gb < G; gb += 4) {
        const int g = gb + gof;
        if (g < G) {
            float4 v = *reinterpret_cast<const float4*>(&pref_s[g * DPB + cf]);
            if (side) {
                v.x = tot4.x - v.x;  v.y = tot4.y - v.y;
                v.z = tot4.z - v.z;  v.w = tot4.w - v.w;
            }
            __stcs(reinterpret_cast<float4*>(ob + (size_t)g * (2 * D)), v);
        }
    }
}

extern "C" void kernel_launch(void* const* d_in, const int* in_sizes, int n_in,
                              void* d_out, int out_size)
{
    const float* x    = (const float*)d_in[0];
    const int*   mask = (const int*)d_in[1];
    float*       out  = (float*)d_out;

    cudaFuncSetAttribute(frag_prefix_kernel,
                         cudaFuncAttributeMaxDynamicSharedMemorySize,
                         (int)SMEM_BYTES);

    frag_prefix_kernel<<<B * NBLOCKS_PER_B, TPB, SMEM_BYTES>>>(x, mask, out);
}

// round 11
// speedup vs baseline: 1.0862x; 1.0862x over previous
#include <cuda_runtime.h>
#include <cstdint>

// x: (S=128, B=512, D=512) f32 ; src_mask: (B,S) int32 (nonzero = padded)
// out: (B, G=127, 2*D) f32
// left[b][g][d]  = prefix_{s<=g} x[s][b][d]*valid[b][s]
// right[b][g][d] = total[b][d] - left[b][g][d]
//
// R10: fully vectorized register-resident variant. Each thread owns 4
// consecutive d-columns (float4) and a 32-long s-chunk (4-way split):
// LDG.128 loads, prefix held in 128 regs, STG.128 streaming stores straight
// from registers (no smem round-trip — R9 showed smem staging just moves LSU
// cost around). Write granularity per (g, side) stays 1KB/block like R5.

namespace {
constexpr int S   = 128;
constexpr int B   = 512;
constexpr int D   = 512;
constexpr int G   = S - 1;        // 127
constexpr int CH  = 4;            // s-chunks per column
constexpr int SC  = S / CH;       // 32 s per chunk
constexpr int DPB = 256;          // d-columns per block
constexpr int VPT = 4;            // d-columns per thread (float4)
constexpr int TPC = DPB / VPT;    // 64 threads per chunk-row
constexpr int TPB = TPC * CH;     // 256 threads
constexpr int NBLOCKS_PER_B = D / DPB;  // 2
}

__global__ __launch_bounds__(TPB, 1)
void frag_prefix_kernel(const float* __restrict__ x,
                        const int*   __restrict__ mask,
                        float*       __restrict__ out)
{
    __shared__ float  valid[S];
    __shared__ float4 partial[CH][TPC];

    const int tid  = threadIdx.x;
    const int b    = blockIdx.x >> 1;          // / NBLOCKS_PER_B
    const int dblk = blockIdx.x & 1;
    const int c    = tid >> 6;                 // s-chunk 0..3 (uniform per 2 warps)
    const int j    = tid & (TPC - 1);          // float4 column index 0..63
    const int d    = dblk * DPB + j * VPT;

    if (tid < S)
        valid[tid] = (mask[b * S + tid] != 0) ? 0.0f : 1.0f;
    __syncthreads();

    // ---- Phase 1: masked float4 prefix of this thread's 32-long s-chunk ----
    // x index: s*B*D + b*D + d. Warp (32 lanes x 16B) = 512B contiguous.
    const float* __restrict__ xp =
        x + (size_t)(c * SC) * (B * D) + (size_t)b * D + d;
    float4 pref[SC];
    float4 p = make_float4(0.f, 0.f, 0.f, 0.f);
    #pragma unroll
    for (int i = 0; i < SC; ++i) {
        const float4 v = __ldcs(reinterpret_cast<const float4*>(
                                    xp + (size_t)i * (B * D)));
        const float m = valid[c * SC + i];
        p.x += v.x * m;  p.y += v.y * m;
        p.z += v.z * m;  p.w += v.w * m;
        pref[i] = p;
    }

    // ---- Exchange chunk sums: carry (earlier chunks) and column total ----
    partial[c][j] = p;
    __syncthreads();
    float4 carry = make_float4(0.f, 0.f, 0.f, 0.f);
    float4 tot   = make_float4(0.f, 0.f, 0.f, 0.f);
    #pragma unroll
    for (int cc = 0; cc < CH; ++cc) {
        const float4 v = partial[cc][j];
        if (cc < c) {
            carry.x += v.x; carry.y += v.y; carry.z += v.z; carry.w += v.w;
        }
        tot.x += v.x; tot.y += v.y; tot.z += v.z; tot.w += v.w;
    }

    // ---- Phase 2: STG.128 streaming stores straight from registers ----
    // Per g, the chunk's 64 threads store 1KB (left) + 1KB (right).
    float* __restrict__ op =
        out + (size_t)b * G * (2 * D) + (size_t)(c * SC) * (2 * D) + d;
    const int gmax = (c == CH - 1) ? SC - 1 : SC;   // skip global g == 127
    #pragma unroll
    for (int i = 0; i < SC; ++i) {
        if (i < gmax) {
            float4 l = pref[i];
            l.x += carry.x; l.y += carry.y; l.z += carry.z; l.w += carry.w;
            float4 r;
            r.x = tot.x - l.x; r.y = tot.y - l.y;
            r.z = tot.z - l.z; r.w = tot.w - l.w;
            __stcs(reinterpret_cast<float4*>(op),     l);
            __stcs(reinterpret_cast<float4*>(op + D), r);
        }
        op += 2 * D;
    }
}

extern "C" void kernel_launch(void* const* d_in, const int* in_sizes, int n_in,
                              void* d_out, int out_size)
{
    const float* x    = (const float*)d_in[0];
    const int*   mask = (const int*)d_in[1];
    float*       out  = (float*)d_out;

    frag_prefix_kernel<<<B * NBLOCKS_PER_B, TPB>>>(x, mask, out);
}